// round 15
// baseline (speedup 1.0000x reference)
#include <cuda_runtime.h>
#include <cuda_fp16.h>
#include <cstdint>

#define NNODES 100000
#define EMAX   1600000
#define NGRAPH 64
#define CAP    96          // bucket capacity per node (deg ~ Poisson(16); P(>96) ~ 1e-17)

// ---------------- device scratch ----------------
__device__ int    g_cnt[NNODES];
__device__ int    g_csrb[NNODES * CAP];   // bucketed CSR (38.4 MB)
__device__ float  g_dis[NNODES];
__device__ __half g_hs1h[NNODES * 32];    // fp16: x @ W1, then scaled in-place to dis*(x@W1)
__device__ __half g_hl[NNODES * 32];      // fp16: dis * lrelu(layer1)
__device__ int    g_pool[NGRAPH * 64];

// ---------------- helpers ----------------
__device__ __forceinline__ int fenc(float v) {
    int i = __float_as_int(v);
    return i >= 0 ? i : (i ^ 0x7FFFFFFF);
}
__device__ __forceinline__ float fdec(int i) {
    return __int_as_float(i >= 0 ? i : (i ^ 0x7FFFFFFF));
}
__device__ __forceinline__ float lrelu(float v) { return v > 0.0f ? v : 0.1f * v; }

#define ENC_NEG_INF ((int)0x807FFFFF)
#define FNEG_INF    __int_as_float(0xFF800000)

// ---------------- kernels ----------------

// fused: bucket CSR fill (atomic-bound) + gemm1 UNSCALED (hides in idle issue slots)
__global__ void k_fillbgemm(const int* __restrict__ src, const int* __restrict__ dst,
                            const float* __restrict__ x, const float* __restrict__ W1,
                            int E, int Nn) {
    __shared__ float sW[128 * 32];
    for (int i = threadIdx.x; i < 128 * 32; i += blockDim.x) sW[i] = W1[i];
    __syncthreads();

    int gtid = blockIdx.x * blockDim.x + threadIdx.x;
    int nthr = gridDim.x * blockDim.x;

    // phase A: bucket fill
    int e4 = E >> 2;
    for (int t = gtid; t < e4; t += nthr) {
        int4 d = reinterpret_cast<const int4*>(dst)[t];
        int4 sc = reinterpret_cast<const int4*>(src)[t];
        int p0 = atomicAdd(&g_cnt[d.x], 1);
        int p1 = atomicAdd(&g_cnt[d.y], 1);
        int p2 = atomicAdd(&g_cnt[d.z], 1);
        int p3 = atomicAdd(&g_cnt[d.w], 1);
        if (p0 < CAP) g_csrb[d.x * CAP + p0] = sc.x;
        if (p1 < CAP) g_csrb[d.y * CAP + p1] = sc.y;
        if (p2 < CAP) g_csrb[d.z * CAP + p2] = sc.z;
        if (p3 < CAP) g_csrb[d.w * CAP + p3] = sc.w;
    }
    for (int e = e4 * 4 + gtid; e < E; e += nthr) {
        int dd = dst[e];
        int p = atomicAdd(&g_cnt[dd], 1);
        if (p < CAP) g_csrb[dd * CAP + p] = src[e];
    }

    // phase B: gemm1 (unscaled), warp per node
    int gw = gtid >> 5;
    int nw = nthr >> 5;
    int lane = threadIdx.x & 31;
    for (int node = gw; node < Nn; node += nw) {
        const float* xr = x + (size_t)node * 128;
        float acc = 0.0f;
#pragma unroll
        for (int kt = 0; kt < 4; kt++) {
            float xk = xr[kt * 32 + lane];
#pragma unroll
            for (int kk = 0; kk < 32; kk++) {
                float xv = __shfl_sync(0xFFFFFFFFu, xk, kk);
                acc = fmaf(xv, sW[(kt * 32 + kk) * 32 + lane], acc);
            }
        }
        g_hs1h[(size_t)node * 32 + lane] = __float2half_rn(acc);
    }
}

// dis = rsqrt(cnt+1); scale hs1 in place by dis; init pool
__global__ void k_disscale(int Nn) {
    int i = blockIdx.x * blockDim.x + threadIdx.x;
    if (i < NGRAPH * 64) g_pool[i] = ENC_NEG_INF;
    int total = Nn * 16;          // half2 elements
    if (i >= total) return;
    int node = i >> 4;
    float d = rsqrtf((float)__ldg(&g_cnt[node]) + 1.0f);
    if ((i & 15) == 0) g_dis[node] = d;
    __half2* p = reinterpret_cast<__half2*>(g_hs1h);
    float2 v = __half22float2(p[i]);
    p[i] = __floats2half2_rn(v.x * d, v.y * d);
}

// layer-1 aggregation + lrelu; stores hl = fp16(dis * lrelu)
__global__ void k_agg1(const float* __restrict__ b1, int Nn) {
    int warp = (blockIdx.x * blockDim.x + threadIdx.x) >> 5;
    int lane = threadIdx.x & 31;
    if (warp >= Nn) return;

    int rs = warp * CAP;
    int cnt = g_cnt[warp];
    if (cnt > CAP) cnt = CAP;
    float a0 = 0.f, a1 = 0.f, a2 = 0.f, a3 = 0.f;
    for (int base = 0; base < cnt; base += 32) {
        int rem = cnt - base;
        int m = rem < 32 ? rem : 32;
        int sidx = 0;
        if (lane < m) sidx = g_csrb[rs + base + lane];
        int k = 0;
        for (; k + 4 <= m; k += 4) {
            int s0 = __shfl_sync(0xFFFFFFFFu, sidx, k);
            int s1 = __shfl_sync(0xFFFFFFFFu, sidx, k + 1);
            int s2 = __shfl_sync(0xFFFFFFFFu, sidx, k + 2);
            int s3 = __shfl_sync(0xFFFFFFFFu, sidx, k + 3);
            a0 += __half2float(__ldg(&g_hs1h[(size_t)s0 * 32 + lane]));
            a1 += __half2float(__ldg(&g_hs1h[(size_t)s1 * 32 + lane]));
            a2 += __half2float(__ldg(&g_hs1h[(size_t)s2 * 32 + lane]));
            a3 += __half2float(__ldg(&g_hs1h[(size_t)s3 * 32 + lane]));
        }
        for (; k < m; k++) {
            int s = __shfl_sync(0xFFFFFFFFu, sidx, k);
            a0 += __half2float(__ldg(&g_hs1h[(size_t)s * 32 + lane]));
        }
    }
    float d = g_dis[warp];
    float acc = (a0 + a1) + (a2 + a3);
    float self = __half2float(g_hs1h[(size_t)warp * 32 + lane]);
    float v = lrelu(d * (acc + self) + b1[lane]);
    g_hl[(size_t)warp * 32 + lane] = __float2half_rn(d * v);
}

// layer-2: gather hl, t = sum + self, one GEMM2 per node, out2 = dis*(t@W2)+b2, fused pool
__global__ void k_agg2(const float* __restrict__ b2, const float* __restrict__ W2,
                       const int* __restrict__ batch, int Nn) {
    __shared__ float sW[32 * 64];
    __shared__ float2 sv[8][32];
    __shared__ int sb[8];
    for (int i = threadIdx.x; i < 32 * 64; i += blockDim.x) sW[i] = W2[i];
    __syncthreads();

    int wid = threadIdx.x >> 5;
    int lane = threadIdx.x & 31;
    int node = blockIdx.x * 8 + wid;
    bool valid = node < Nn;

    if (lane == 0) sb[wid] = valid ? batch[node] : -1;

    if (valid) {
        int rs = node * CAP;
        int cnt = g_cnt[node];
        if (cnt > CAP) cnt = CAP;
        float a0 = 0.f, a1 = 0.f, a2 = 0.f, a3 = 0.f;
        for (int base = 0; base < cnt; base += 32) {
            int rem = cnt - base;
            int m = rem < 32 ? rem : 32;
            int sidx = 0;
            if (lane < m) sidx = g_csrb[rs + base + lane];
            int k = 0;
            for (; k + 4 <= m; k += 4) {
                int s0 = __shfl_sync(0xFFFFFFFFu, sidx, k);
                int s1 = __shfl_sync(0xFFFFFFFFu, sidx, k + 1);
                int s2 = __shfl_sync(0xFFFFFFFFu, sidx, k + 2);
                int s3 = __shfl_sync(0xFFFFFFFFu, sidx, k + 3);
                a0 += __half2float(__ldg(&g_hl[(size_t)s0 * 32 + lane]));
                a1 += __half2float(__ldg(&g_hl[(size_t)s1 * 32 + lane]));
                a2 += __half2float(__ldg(&g_hl[(size_t)s2 * 32 + lane]));
                a3 += __half2float(__ldg(&g_hl[(size_t)s3 * 32 + lane]));
            }
            for (; k < m; k++) {
                int s = __shfl_sync(0xFFFFFFFFu, sidx, k);
                a0 += __half2float(__ldg(&g_hl[(size_t)s * 32 + lane]));
            }
        }
        float selfv = __half2float(g_hl[(size_t)node * 32 + lane]);
        float t = (a0 + a1) + (a2 + a3) + selfv;

        const float2* sWp = reinterpret_cast<const float2*>(sW);
        float o0 = 0.f, o1 = 0.f;
#pragma unroll
        for (int kk = 0; kk < 32; kk++) {
            float xv = __shfl_sync(0xFFFFFFFFu, t, kk);
            float2 w = sWp[kk * 32 + lane];
            o0 = fmaf(xv, w.x, o0);
            o1 = fmaf(xv, w.y, o1);
        }
        float d = g_dis[node];
        float2 bb = reinterpret_cast<const float2*>(b2)[lane];
        float2 o;
        o.x = d * o0 + bb.x;
        o.y = d * o1 + bb.y;
        sv[wid][lane] = o;
    }
    __syncthreads();

    if (threadIdx.x < 64) {
        int f = threadIdx.x;
        int half_ = f >> 1;
        int comp = f & 1;
        int curg = -1;
        float mx = FNEG_INF;
        for (int w = 0; w < 8; w++) {
            int bg = sb[w];
            if (bg < 0) continue;
            float2 p = sv[w][half_];
            float val = comp ? p.y : p.x;
            if (bg != curg) {
                if (curg >= 0) atomicMax(&g_pool[curg * 64 + f], fenc(mx));
                curg = bg;
                mx = FNEG_INF;
            }
            mx = fmaxf(mx, val);
        }
        if (curg >= 0) atomicMax(&g_pool[curg * 64 + f], fenc(mx));
    }
}

// MLP head, one block per graph: 64 -> 128 -> 64 -> 1
__global__ void k_mlp(const float* __restrict__ Wl1, const float* __restrict__ bl1,
                      const float* __restrict__ Wl2, const float* __restrict__ bl2,
                      const float* __restrict__ Wl3, const float* __restrict__ bl3,
                      float* __restrict__ out) {
    __shared__ float sg[64];
    __shared__ float st1[128];
    __shared__ float st2[64];
    int g = blockIdx.x;
    int t = threadIdx.x;

    if (t < 64) sg[t] = fdec(g_pool[g * 64 + t]);
    __syncthreads();
    {
        float s = bl1[t];
#pragma unroll 8
        for (int k = 0; k < 64; k++) s = fmaf(sg[k], Wl1[k * 128 + t], s);
        st1[t] = lrelu(s);
    }
    __syncthreads();
    if (t < 64) {
        float s = bl2[t];
#pragma unroll 8
        for (int k = 0; k < 128; k++) s = fmaf(st1[k], Wl2[k * 64 + t], s);
        st2[t] = lrelu(s);
    }
    __syncthreads();
    __shared__ float red[2];
    if (t < 64) {
        float p = st2[t] * Wl3[t];
#pragma unroll
        for (int off = 16; off > 0; off >>= 1)
            p += __shfl_down_sync(0xFFFFFFFFu, p, off);
        if ((t & 31) == 0) red[t >> 5] = p;
    }
    __syncthreads();
    if (t == 0) out[g] = red[0] + red[1] + bl3[0];
}

// ---------------- launch (single stream) ----------------
// kernel order: fillbgemm(1), disscale(2), agg1(3), agg2(4) <- ncu capture, mlp(5)
extern "C" void kernel_launch(void* const* d_in, const int* in_sizes, int n_in,
                              void* d_out, int out_size) {
    const float* x   = (const float*)d_in[0];
    const int*   ei  = (const int*)d_in[1];
    const int*   bat = (const int*)d_in[2];
    const float* W1  = (const float*)d_in[3];
    const float* b1  = (const float*)d_in[4];
    const float* W2  = (const float*)d_in[5];
    const float* b2  = (const float*)d_in[6];
    const float* Wl1 = (const float*)d_in[7];
    const float* bl1 = (const float*)d_in[8];
    const float* Wl2 = (const float*)d_in[9];
    const float* bl2 = (const float*)d_in[10];
    const float* Wl3 = (const float*)d_in[11];
    const float* bl3 = (const float*)d_in[12];
    float* out = (float*)d_out;

    int Nn = in_sizes[0] / 128;
    int E  = in_sizes[1] / 2;
    const int* src = ei;
    const int* dst = ei + E;

    static void* cntPtr = nullptr;
    if (cntPtr == nullptr) cudaGetSymbolAddress(&cntPtr, g_cnt);

    cudaMemsetAsync(cntPtr, 0, NNODES * sizeof(int), 0);
    k_fillbgemm<<<(Nn + 7) / 8, 256>>>(src, dst, x, W1, E, Nn);
    k_disscale<<<(Nn * 16 + 255) / 256, 256>>>(Nn);
    k_agg1<<<(Nn + 7) / 8, 256>>>(b1, Nn);
    k_agg2<<<(Nn + 7) / 8, 256>>>(b2, W2, bat, Nn);
    k_mlp<<<NGRAPH, 128>>>(Wl1, bl1, Wl2, bl2, Wl3, bl3, out);
}

// round 16
// speedup vs baseline: 1.4106x; 1.4106x over previous
#include <cuda_runtime.h>
#include <cuda_fp16.h>
#include <cstdint>

#define NNODES 100000
#define EMAX   1600000
#define NGRAPH 64

// ---------------- device scratch ----------------
__device__ int    g_cnt[NNODES];
__device__ int    g_rowstart[NNODES];
__device__ int    g_cursor[NNODES];
__device__ unsigned long long g_state[128];   // decoupled-lookback state
__device__ int    g_csrsrc[EMAX];
__device__ float  g_dis[NNODES];
__device__ __half g_hs1h[NNODES * 32];    // fp16: dis * (x @ W1)       (row = 64B)
__device__ __half g_hl[NNODES * 32];      // fp16: dis * lrelu(layer1)  (row = 64B)
__device__ int    g_pool[NGRAPH * 64];

#define FLAG_A (1ull << 62)
#define FLAG_P (2ull << 62)

// ---------------- helpers ----------------
__device__ __forceinline__ int fenc(float v) {
    int i = __float_as_int(v);
    return i >= 0 ? i : (i ^ 0x7FFFFFFF);
}
__device__ __forceinline__ float fdec(int i) {
    return __int_as_float(i >= 0 ? i : (i ^ 0x7FFFFFFF));
}
__device__ __forceinline__ float lrelu(float v) { return v > 0.0f ? v : 0.1f * v; }

#define ENC_NEG_INF ((int)0x807FFFFF)
#define FNEG_INF    __int_as_float(0xFF800000)

// ---------------- kernels ----------------

__global__ void k_nop() {}

// histogram of dst (int4-vectorized); block 0 also zeroes scan state + inits pool
__global__ void k_count(const int* __restrict__ dst, int E) {
    if (blockIdx.x == 0) {
        if (threadIdx.x < 128) g_state[threadIdx.x] = 0ull;
        for (int i = threadIdx.x; i < NGRAPH * 64; i += 256) g_pool[i] = ENC_NEG_INF;
    }
    int t = blockIdx.x * blockDim.x + threadIdx.x;
    int e4 = E >> 2;
    if (t < e4) {
        int4 d = reinterpret_cast<const int4*>(dst)[t];
        atomicAdd(&g_cnt[d.x], 1);
        atomicAdd(&g_cnt[d.y], 1);
        atomicAdd(&g_cnt[d.z], 1);
        atomicAdd(&g_cnt[d.w], 1);
    } else {
        int e = e4 * 4 + (t - e4);
        if (e < E) atomicAdd(&g_cnt[dst[e]], 1);
    }
}

// single-pass decoupled-lookback exclusive scan of g_cnt -> g_rowstart/g_cursor; also g_dis
__global__ void k_scanlb(int Nn) {
    __shared__ int sT[256];
    __shared__ int sPrefix;
    int t = threadIdx.x;
    int b = blockIdx.x;
    int base = b * 1024 + t * 4;
    int v0 = (base + 0 < Nn) ? g_cnt[base + 0] : 0;
    int v1 = (base + 1 < Nn) ? g_cnt[base + 1] : 0;
    int v2 = (base + 2 < Nn) ? g_cnt[base + 2] : 0;
    int v3 = (base + 3 < Nn) ? g_cnt[base + 3] : 0;
    if (base + 0 < Nn) g_dis[base + 0] = rsqrtf((float)v0 + 1.0f);
    if (base + 1 < Nn) g_dis[base + 1] = rsqrtf((float)v1 + 1.0f);
    if (base + 2 < Nn) g_dis[base + 2] = rsqrtf((float)v2 + 1.0f);
    if (base + 3 < Nn) g_dis[base + 3] = rsqrtf((float)v3 + 1.0f);
    int tot = v0 + v1 + v2 + v3;
    sT[t] = tot;
    __syncthreads();
    for (int off = 1; off < 256; off <<= 1) {
        int x = 0;
        if (t >= off) x = sT[t - off];
        __syncthreads();
        if (t >= off) sT[t] += x;
        __syncthreads();
    }
    int myExc = sT[t] - tot;
    int blockTotal = sT[255];

    if (t == 0) {
        if (b == 0) {
            atomicExch(&g_state[0], FLAG_P | (unsigned int)blockTotal);
            sPrefix = 0;
        } else {
            atomicExch(&g_state[b], FLAG_A | (unsigned int)blockTotal);
            int run = 0;
            int idx = b - 1;
            while (true) {
                unsigned long long s = atomicAdd(&g_state[idx], 0ull);
                unsigned long long fl = s >> 62;
                if (fl == 2ull) { run += (int)(s & 0xFFFFFFFFull); break; }
                if (fl == 1ull) { run += (int)(s & 0xFFFFFFFFull); idx--; }
            }
            atomicExch(&g_state[b], FLAG_P | (unsigned int)(run + blockTotal));
            sPrefix = run;
        }
    }
    __syncthreads();

    int rs = sPrefix + myExc;
    if (base + 0 < Nn) { g_rowstart[base + 0] = rs; g_cursor[base + 0] = rs; } rs += v0;
    if (base + 1 < Nn) { g_rowstart[base + 1] = rs; g_cursor[base + 1] = rs; } rs += v1;
    if (base + 2 < Nn) { g_rowstart[base + 2] = rs; g_cursor[base + 2] = rs; } rs += v2;
    if (base + 3 < Nn) { g_rowstart[base + 3] = rs; g_cursor[base + 3] = rs; }
}

// scatter src ids into packed CSR (int4-vectorized)
__global__ void k_fill(const int* __restrict__ src, const int* __restrict__ dst, int E) {
    int t = blockIdx.x * blockDim.x + threadIdx.x;
    int e4 = E >> 2;
    if (t < e4) {
        int4 d = reinterpret_cast<const int4*>(dst)[t];
        int4 sc = reinterpret_cast<const int4*>(src)[t];
        g_csrsrc[atomicAdd(&g_cursor[d.x], 1)] = sc.x;
        g_csrsrc[atomicAdd(&g_cursor[d.y], 1)] = sc.y;
        g_csrsrc[atomicAdd(&g_cursor[d.z], 1)] = sc.z;
        g_csrsrc[atomicAdd(&g_cursor[d.w], 1)] = sc.w;
    } else {
        int e = e4 * 4 + (t - e4);
        if (e < E) g_csrsrc[atomicAdd(&g_cursor[dst[e]], 1)] = src[e];
    }
}

// hs1 = fp16( dis * (x @ W1) )
__global__ void k_gemm1(const float* __restrict__ x, const float* __restrict__ W1, int Nn) {
    __shared__ float sW[128 * 32];
    for (int i = threadIdx.x; i < 128 * 32; i += blockDim.x) sW[i] = W1[i];
    __syncthreads();
    int warp = (blockIdx.x * blockDim.x + threadIdx.x) >> 5;
    int lane = threadIdx.x & 31;
    if (warp >= Nn) return;
    const float* xr = x + (size_t)warp * 128;
    float acc = 0.0f;
#pragma unroll
    for (int kt = 0; kt < 4; kt++) {
        float xk = xr[kt * 32 + lane];
#pragma unroll
        for (int kk = 0; kk < 32; kk++) {
            float xv = __shfl_sync(0xFFFFFFFFu, xk, kk);
            acc = fmaf(xv, sW[(kt * 32 + kk) * 32 + lane], acc);
        }
    }
    g_hs1h[(size_t)warp * 32 + lane] = __float2half_rn(g_dis[warp] * acc);
}

// layer-1 aggregation + lrelu; stores hl = fp16(dis * lrelu)
__global__ void k_agg1(const float* __restrict__ b1, int Nn) {
    int warp = (blockIdx.x * blockDim.x + threadIdx.x) >> 5;
    int lane = threadIdx.x & 31;
    if (warp >= Nn) return;

    int rs = g_rowstart[warp];
    int cnt = g_cnt[warp];
    float a0 = 0.f, a1 = 0.f, a2 = 0.f, a3 = 0.f;
    for (int base = 0; base < cnt; base += 32) {
        int rem = cnt - base;
        int m = rem < 32 ? rem : 32;
        int sidx = 0;
        if (lane < m) sidx = g_csrsrc[rs + base + lane];
        int k = 0;
        for (; k + 4 <= m; k += 4) {
            int s0 = __shfl_sync(0xFFFFFFFFu, sidx, k);
            int s1 = __shfl_sync(0xFFFFFFFFu, sidx, k + 1);
            int s2 = __shfl_sync(0xFFFFFFFFu, sidx, k + 2);
            int s3 = __shfl_sync(0xFFFFFFFFu, sidx, k + 3);
            a0 += __half2float(__ldg(&g_hs1h[(size_t)s0 * 32 + lane]));
            a1 += __half2float(__ldg(&g_hs1h[(size_t)s1 * 32 + lane]));
            a2 += __half2float(__ldg(&g_hs1h[(size_t)s2 * 32 + lane]));
            a3 += __half2float(__ldg(&g_hs1h[(size_t)s3 * 32 + lane]));
        }
        for (; k < m; k++) {
            int s = __shfl_sync(0xFFFFFFFFu, sidx, k);
            a0 += __half2float(__ldg(&g_hs1h[(size_t)s * 32 + lane]));
        }
    }
    float d = g_dis[warp];
    float acc = (a0 + a1) + (a2 + a3);
    float self = __half2float(g_hs1h[(size_t)warp * 32 + lane]);
    float v = lrelu(d * (acc + self) + b1[lane]);
    g_hl[(size_t)warp * 32 + lane] = __float2half_rn(d * v);
}

// layer-2: gather hl, t = sum + self, one GEMM2 per node, out2 = dis*(t@W2)+b2, fused pool
__global__ void k_agg2(const float* __restrict__ b2, const float* __restrict__ W2,
                       const int* __restrict__ batch, int Nn) {
    __shared__ float sW[32 * 64];
    __shared__ float2 sv[8][32];
    __shared__ int sb[8];
    for (int i = threadIdx.x; i < 32 * 64; i += blockDim.x) sW[i] = W2[i];
    __syncthreads();

    int wid = threadIdx.x >> 5;
    int lane = threadIdx.x & 31;
    int node = blockIdx.x * 8 + wid;
    bool valid = node < Nn;

    if (lane == 0) sb[wid] = valid ? batch[node] : -1;

    if (valid) {
        int rs = g_rowstart[node];
        int cnt = g_cnt[node];
        float a0 = 0.f, a1 = 0.f, a2 = 0.f, a3 = 0.f;
        for (int base = 0; base < cnt; base += 32) {
            int rem = cnt - base;
            int m = rem < 32 ? rem : 32;
            int sidx = 0;
            if (lane < m) sidx = g_csrsrc[rs + base + lane];
            int k = 0;
            for (; k + 4 <= m; k += 4) {
                int s0 = __shfl_sync(0xFFFFFFFFu, sidx, k);
                int s1 = __shfl_sync(0xFFFFFFFFu, sidx, k + 1);
                int s2 = __shfl_sync(0xFFFFFFFFu, sidx, k + 2);
                int s3 = __shfl_sync(0xFFFFFFFFu, sidx, k + 3);
                a0 += __half2float(__ldg(&g_hl[(size_t)s0 * 32 + lane]));
                a1 += __half2float(__ldg(&g_hl[(size_t)s1 * 32 + lane]));
                a2 += __half2float(__ldg(&g_hl[(size_t)s2 * 32 + lane]));
                a3 += __half2float(__ldg(&g_hl[(size_t)s3 * 32 + lane]));
            }
            for (; k < m; k++) {
                int s = __shfl_sync(0xFFFFFFFFu, sidx, k);
                a0 += __half2float(__ldg(&g_hl[(size_t)s * 32 + lane]));
            }
        }
        float selfv = __half2float(g_hl[(size_t)node * 32 + lane]);
        float t = (a0 + a1) + (a2 + a3) + selfv;

        const float2* sWp = reinterpret_cast<const float2*>(sW);
        float o0 = 0.f, o1 = 0.f;
#pragma unroll
        for (int kk = 0; kk < 32; kk++) {
            float xv = __shfl_sync(0xFFFFFFFFu, t, kk);
            float2 w = sWp[kk * 32 + lane];
            o0 = fmaf(xv, w.x, o0);
            o1 = fmaf(xv, w.y, o1);
        }
        float d = g_dis[node];
        float2 bb = reinterpret_cast<const float2*>(b2)[lane];
        float2 o;
        o.x = d * o0 + bb.x;
        o.y = d * o1 + bb.y;
        sv[wid][lane] = o;
    }
    __syncthreads();

    if (threadIdx.x < 64) {
        int f = threadIdx.x;
        int half_ = f >> 1;
        int comp = f & 1;
        int curg = -1;
        float mx = FNEG_INF;
        for (int w = 0; w < 8; w++) {
            int bg = sb[w];
            if (bg < 0) continue;
            float2 p = sv[w][half_];
            float val = comp ? p.y : p.x;
            if (bg != curg) {
                if (curg >= 0) atomicMax(&g_pool[curg * 64 + f], fenc(mx));
                curg = bg;
                mx = FNEG_INF;
            }
            mx = fmaxf(mx, val);
        }
        if (curg >= 0) atomicMax(&g_pool[curg * 64 + f], fenc(mx));
    }
}

// MLP head, one block per graph: 64 -> 128 -> 64 -> 1
__global__ void k_mlp(const float* __restrict__ Wl1, const float* __restrict__ bl1,
                      const float* __restrict__ Wl2, const float* __restrict__ bl2,
                      const float* __restrict__ Wl3, const float* __restrict__ bl3,
                      float* __restrict__ out) {
    __shared__ float sg[64];
    __shared__ float st1[128];
    __shared__ float st2[64];
    int g = blockIdx.x;
    int t = threadIdx.x;

    if (t < 64) sg[t] = fdec(g_pool[g * 64 + t]);
    __syncthreads();
    {
        float s = bl1[t];
#pragma unroll 8
        for (int k = 0; k < 64; k++) s = fmaf(sg[k], Wl1[k * 128 + t], s);
        st1[t] = lrelu(s);
    }
    __syncthreads();
    if (t < 64) {
        float s = bl2[t];
#pragma unroll 8
        for (int k = 0; k < 128; k++) s = fmaf(st1[k], Wl2[k * 64 + t], s);
        st2[t] = lrelu(s);
    }
    __syncthreads();
    __shared__ float red[2];
    if (t < 64) {
        float p = st2[t] * Wl3[t];
#pragma unroll
        for (int off = 16; off > 0; off >>= 1)
            p += __shfl_down_sync(0xFFFFFFFFu, p, off);
        if ((t & 31) == 0) red[t >> 5] = p;
    }
    __syncthreads();
    if (t == 0) out[g] = red[0] + red[1] + bl3[0];
}

// ---------------- launch ----------------
// s2: memset, count, scanlb(evDis), fill(evCSR)
// main: gemm1(0) [waits evDis, overlaps fill], nop(1), agg1(2) [waits evCSR],
//       agg2(3) <- ncu capture, mlp(4)
extern "C" void kernel_launch(void* const* d_in, const int* in_sizes, int n_in,
                              void* d_out, int out_size) {
    const float* x   = (const float*)d_in[0];
    const int*   ei  = (const int*)d_in[1];
    const int*   bat = (const int*)d_in[2];
    const float* W1  = (const float*)d_in[3];
    const float* b1  = (const float*)d_in[4];
    const float* W2  = (const float*)d_in[5];
    const float* b2  = (const float*)d_in[6];
    const float* Wl1 = (const float*)d_in[7];
    const float* bl1 = (const float*)d_in[8];
    const float* Wl2 = (const float*)d_in[9];
    const float* bl2 = (const float*)d_in[10];
    const float* Wl3 = (const float*)d_in[11];
    const float* bl3 = (const float*)d_in[12];
    float* out = (float*)d_out;

    int Nn = in_sizes[0] / 128;
    int E  = in_sizes[1] / 2;
    const int* src = ei;
    const int* dst = ei + E;
    int NB = (Nn + 1023) / 1024;

    static cudaStream_t s2 = nullptr;
    static cudaEvent_t evFork = nullptr, evDis = nullptr, evCSR = nullptr;
    static void* cntPtr = nullptr;
    if (s2 == nullptr) {
        cudaStreamCreateWithFlags(&s2, cudaStreamNonBlocking);
        cudaEventCreateWithFlags(&evFork, cudaEventDisableTiming);
        cudaEventCreateWithFlags(&evDis, cudaEventDisableTiming);
        cudaEventCreateWithFlags(&evCSR, cudaEventDisableTiming);
        cudaGetSymbolAddress(&cntPtr, g_cnt);
    }

    // fork s2 off the captured (main) stream
    cudaEventRecord(evFork, 0);
    cudaStreamWaitEvent(s2, evFork, 0);

    // s2: CSR build chain
    cudaMemsetAsync(cntPtr, 0, NNODES * sizeof(int), s2);
    {
        int nThreads = (E >> 2) + (E & 3);
        k_count<<<(nThreads + 255) / 256, 256, 0, s2>>>(dst, E);
    }
    k_scanlb<<<NB, 256, 0, s2>>>(Nn);          // dis ready here
    cudaEventRecord(evDis, s2);
    {
        int nThreads = (E >> 2) + (E & 3);
        k_fill<<<(nThreads + 255) / 256, 256, 0, s2>>>(src, dst, E);
    }
    cudaEventRecord(evCSR, s2);

    // main: gemm1 (waits dis) overlaps fill on s2
    cudaStreamWaitEvent(0, evDis, 0);
    k_gemm1<<<(Nn + 7) / 8, 256>>>(x, W1, Nn);       // main idx 0
    k_nop<<<1, 32>>>();                               // main idx 1

    // main: aggregation tail (waits CSR)
    cudaStreamWaitEvent(0, evCSR, 0);
    k_agg1<<<(Nn + 7) / 8, 256>>>(b1, Nn);           // main idx 2
    k_agg2<<<(Nn + 7) / 8, 256>>>(b2, W2, bat, Nn);  // main idx 3  <- ncu capture
    k_mlp<<<NGRAPH, 128>>>(Wl1, bl1, Wl2, bl2, Wl3, bl3, out);  // main idx 4
}

// round 17
// speedup vs baseline: 1.6783x; 1.1897x over previous
#include <cuda_runtime.h>
#include <cuda_fp16.h>
#include <cstdint>

#define NNODES 100000
#define EMAX   1600000
#define NGRAPH 64

// ---------------- device scratch ----------------
__device__ int    g_cnt[NNODES];
__device__ int    g_rowstart[NNODES];
__device__ int    g_cursor[NNODES];
__device__ unsigned long long g_state[128];   // decoupled-lookback state
__device__ int    g_csrsrc[EMAX];
__device__ float  g_dis[NNODES];
__device__ __half g_hs1h[NNODES * 32];    // fp16: dis * (x @ W1)       (row = 64B)
__device__ __half g_hl[NNODES * 32];      // fp16: dis * lrelu(layer1)  (row = 64B)
__device__ int    g_pool[NGRAPH * 64];

#define FLAG_A (1ull << 62)
#define FLAG_P (2ull << 62)

// ---------------- helpers ----------------
__device__ __forceinline__ int fenc(float v) {
    int i = __float_as_int(v);
    return i >= 0 ? i : (i ^ 0x7FFFFFFF);
}
__device__ __forceinline__ float fdec(int i) {
    return __int_as_float(i >= 0 ? i : (i ^ 0x7FFFFFFF));
}
__device__ __forceinline__ float lrelu(float v) { return v > 0.0f ? v : 0.1f * v; }

#define ENC_NEG_INF ((int)0x807FFFFF)
#define FNEG_INF    __int_as_float(0xFF800000)

// ---------------- kernels ----------------

__global__ void k_nop() {}

// histogram of dst (int4-vectorized); block 0 also zeroes scan state + inits pool
__global__ void k_count(const int* __restrict__ dst, int E) {
    if (blockIdx.x == 0) {
        if (threadIdx.x < 128) g_state[threadIdx.x] = 0ull;
        for (int i = threadIdx.x; i < NGRAPH * 64; i += 256) g_pool[i] = ENC_NEG_INF;
    }
    int t = blockIdx.x * blockDim.x + threadIdx.x;
    int e4 = E >> 2;
    if (t < e4) {
        int4 d = reinterpret_cast<const int4*>(dst)[t];
        atomicAdd(&g_cnt[d.x], 1);
        atomicAdd(&g_cnt[d.y], 1);
        atomicAdd(&g_cnt[d.z], 1);
        atomicAdd(&g_cnt[d.w], 1);
    } else {
        int e = e4 * 4 + (t - e4);
        if (e < E) atomicAdd(&g_cnt[dst[e]], 1);
    }
}

// single-pass decoupled-lookback exclusive scan of g_cnt -> g_rowstart/g_cursor; also g_dis
__global__ void k_scanlb(int Nn) {
    __shared__ int sT[256];
    __shared__ int sPrefix;
    int t = threadIdx.x;
    int b = blockIdx.x;
    int base = b * 1024 + t * 4;
    int v0 = (base + 0 < Nn) ? g_cnt[base + 0] : 0;
    int v1 = (base + 1 < Nn) ? g_cnt[base + 1] : 0;
    int v2 = (base + 2 < Nn) ? g_cnt[base + 2] : 0;
    int v3 = (base + 3 < Nn) ? g_cnt[base + 3] : 0;
    if (base + 0 < Nn) g_dis[base + 0] = rsqrtf((float)v0 + 1.0f);
    if (base + 1 < Nn) g_dis[base + 1] = rsqrtf((float)v1 + 1.0f);
    if (base + 2 < Nn) g_dis[base + 2] = rsqrtf((float)v2 + 1.0f);
    if (base + 3 < Nn) g_dis[base + 3] = rsqrtf((float)v3 + 1.0f);
    int tot = v0 + v1 + v2 + v3;
    sT[t] = tot;
    __syncthreads();
    for (int off = 1; off < 256; off <<= 1) {
        int x = 0;
        if (t >= off) x = sT[t - off];
        __syncthreads();
        if (t >= off) sT[t] += x;
        __syncthreads();
    }
    int myExc = sT[t] - tot;
    int blockTotal = sT[255];

    if (t == 0) {
        if (b == 0) {
            atomicExch(&g_state[0], FLAG_P | (unsigned int)blockTotal);
            sPrefix = 0;
        } else {
            atomicExch(&g_state[b], FLAG_A | (unsigned int)blockTotal);
            int run = 0;
            int idx = b - 1;
            while (true) {
                unsigned long long s = atomicAdd(&g_state[idx], 0ull);
                unsigned long long fl = s >> 62;
                if (fl == 2ull) { run += (int)(s & 0xFFFFFFFFull); break; }
                if (fl == 1ull) { run += (int)(s & 0xFFFFFFFFull); idx--; }
            }
            atomicExch(&g_state[b], FLAG_P | (unsigned int)(run + blockTotal));
            sPrefix = run;
        }
    }
    __syncthreads();

    int rs = sPrefix + myExc;
    if (base + 0 < Nn) { g_rowstart[base + 0] = rs; g_cursor[base + 0] = rs; } rs += v0;
    if (base + 1 < Nn) { g_rowstart[base + 1] = rs; g_cursor[base + 1] = rs; } rs += v1;
    if (base + 2 < Nn) { g_rowstart[base + 2] = rs; g_cursor[base + 2] = rs; } rs += v2;
    if (base + 3 < Nn) { g_rowstart[base + 3] = rs; g_cursor[base + 3] = rs; }
}

// scatter src ids into packed CSR (int4-vectorized)
__global__ void k_fill(const int* __restrict__ src, const int* __restrict__ dst, int E) {
    int t = blockIdx.x * blockDim.x + threadIdx.x;
    int e4 = E >> 2;
    if (t < e4) {
        int4 d = reinterpret_cast<const int4*>(dst)[t];
        int4 sc = reinterpret_cast<const int4*>(src)[t];
        g_csrsrc[atomicAdd(&g_cursor[d.x], 1)] = sc.x;
        g_csrsrc[atomicAdd(&g_cursor[d.y], 1)] = sc.y;
        g_csrsrc[atomicAdd(&g_cursor[d.z], 1)] = sc.z;
        g_csrsrc[atomicAdd(&g_cursor[d.w], 1)] = sc.w;
    } else {
        int e = e4 * 4 + (t - e4);
        if (e < E) g_csrsrc[atomicAdd(&g_cursor[dst[e]], 1)] = src[e];
    }
}

// hs1 = fp16(dis * (x @ W1)) — 4 nodes per warp: 1 LDS serves 4 FMAs
__global__ void k_gemm1(const float* __restrict__ x, const float* __restrict__ W1, int Nn) {
    __shared__ float sW[128 * 32];
    for (int i = threadIdx.x; i < 128 * 32; i += blockDim.x) sW[i] = W1[i];
    __syncthreads();
    int warp = (blockIdx.x * blockDim.x + threadIdx.x) >> 5;
    int lane = threadIdx.x & 31;
    int n0 = warp * 4;
    if (n0 >= Nn) return;
    // clamp node indices for safe loads; mask stores at the end
    int n1 = n0 + 1 < Nn ? n0 + 1 : Nn - 1;
    int n2 = n0 + 2 < Nn ? n0 + 2 : Nn - 1;
    int n3 = n0 + 3 < Nn ? n0 + 3 : Nn - 1;

    const float* x0 = x + (size_t)n0 * 128;
    const float* x1 = x + (size_t)n1 * 128;
    const float* x2 = x + (size_t)n2 * 128;
    const float* x3 = x + (size_t)n3 * 128;

    float acc0 = 0.f, acc1 = 0.f, acc2 = 0.f, acc3 = 0.f;
#pragma unroll
    for (int kt = 0; kt < 4; kt++) {
        float xk0 = x0[kt * 32 + lane];
        float xk1 = x1[kt * 32 + lane];
        float xk2 = x2[kt * 32 + lane];
        float xk3 = x3[kt * 32 + lane];
#pragma unroll
        for (int kk = 0; kk < 32; kk++) {
            float w = sW[(kt * 32 + kk) * 32 + lane];   // one LDS, four consumers
            acc0 = fmaf(__shfl_sync(0xFFFFFFFFu, xk0, kk), w, acc0);
            acc1 = fmaf(__shfl_sync(0xFFFFFFFFu, xk1, kk), w, acc1);
            acc2 = fmaf(__shfl_sync(0xFFFFFFFFu, xk2, kk), w, acc2);
            acc3 = fmaf(__shfl_sync(0xFFFFFFFFu, xk3, kk), w, acc3);
        }
    }
    g_hs1h[(size_t)n0 * 32 + lane] = __float2half_rn(g_dis[n0] * acc0);
    if (n0 + 1 < Nn) g_hs1h[(size_t)n1 * 32 + lane] = __float2half_rn(g_dis[n1] * acc1);
    if (n0 + 2 < Nn) g_hs1h[(size_t)n2 * 32 + lane] = __float2half_rn(g_dis[n2] * acc2);
    if (n0 + 3 < Nn) g_hs1h[(size_t)n3 * 32 + lane] = __float2half_rn(g_dis[n3] * acc3);
}

// layer-1 aggregation + lrelu; stores hl = fp16(dis * lrelu)
__global__ void k_agg1(const float* __restrict__ b1, int Nn) {
    int warp = (blockIdx.x * blockDim.x + threadIdx.x) >> 5;
    int lane = threadIdx.x & 31;
    if (warp >= Nn) return;

    int rs = g_rowstart[warp];
    int cnt = g_cnt[warp];
    float a0 = 0.f, a1 = 0.f, a2 = 0.f, a3 = 0.f;
    for (int base = 0; base < cnt; base += 32) {
        int rem = cnt - base;
        int m = rem < 32 ? rem : 32;
        int sidx = 0;
        if (lane < m) sidx = g_csrsrc[rs + base + lane];
        int k = 0;
        for (; k + 4 <= m; k += 4) {
            int s0 = __shfl_sync(0xFFFFFFFFu, sidx, k);
            int s1 = __shfl_sync(0xFFFFFFFFu, sidx, k + 1);
            int s2 = __shfl_sync(0xFFFFFFFFu, sidx, k + 2);
            int s3 = __shfl_sync(0xFFFFFFFFu, sidx, k + 3);
            a0 += __half2float(__ldg(&g_hs1h[(size_t)s0 * 32 + lane]));
            a1 += __half2float(__ldg(&g_hs1h[(size_t)s1 * 32 + lane]));
            a2 += __half2float(__ldg(&g_hs1h[(size_t)s2 * 32 + lane]));
            a3 += __half2float(__ldg(&g_hs1h[(size_t)s3 * 32 + lane]));
        }
        for (; k < m; k++) {
            int s = __shfl_sync(0xFFFFFFFFu, sidx, k);
            a0 += __half2float(__ldg(&g_hs1h[(size_t)s * 32 + lane]));
        }
    }
    float d = g_dis[warp];
    float acc = (a0 + a1) + (a2 + a3);
    float self = __half2float(g_hs1h[(size_t)warp * 32 + lane]);
    float v = lrelu(d * (acc + self) + b1[lane]);
    g_hl[(size_t)warp * 32 + lane] = __float2half_rn(d * v);
}

// layer-2: gather hl, t = sum + self, one GEMM2 per node, out2 = dis*(t@W2)+b2, fused pool
__global__ void k_agg2(const float* __restrict__ b2, const float* __restrict__ W2,
                       const int* __restrict__ batch, int Nn) {
    __shared__ float sW[32 * 64];
    __shared__ float2 sv[8][32];
    __shared__ int sb[8];
    for (int i = threadIdx.x; i < 32 * 64; i += blockDim.x) sW[i] = W2[i];
    __syncthreads();

    int wid = threadIdx.x >> 5;
    int lane = threadIdx.x & 31;
    int node = blockIdx.x * 8 + wid;
    bool valid = node < Nn;

    if (lane == 0) sb[wid] = valid ? batch[node] : -1;

    if (valid) {
        int rs = g_rowstart[node];
        int cnt = g_cnt[node];
        float a0 = 0.f, a1 = 0.f, a2 = 0.f, a3 = 0.f;
        for (int base = 0; base < cnt; base += 32) {
            int rem = cnt - base;
            int m = rem < 32 ? rem : 32;
            int sidx = 0;
            if (lane < m) sidx = g_csrsrc[rs + base + lane];
            int k = 0;
            for (; k + 4 <= m; k += 4) {
                int s0 = __shfl_sync(0xFFFFFFFFu, sidx, k);
                int s1 = __shfl_sync(0xFFFFFFFFu, sidx, k + 1);
                int s2 = __shfl_sync(0xFFFFFFFFu, sidx, k + 2);
                int s3 = __shfl_sync(0xFFFFFFFFu, sidx, k + 3);
                a0 += __half2float(__ldg(&g_hl[(size_t)s0 * 32 + lane]));
                a1 += __half2float(__ldg(&g_hl[(size_t)s1 * 32 + lane]));
                a2 += __half2float(__ldg(&g_hl[(size_t)s2 * 32 + lane]));
                a3 += __half2float(__ldg(&g_hl[(size_t)s3 * 32 + lane]));
            }
            for (; k < m; k++) {
                int s = __shfl_sync(0xFFFFFFFFu, sidx, k);
                a0 += __half2float(__ldg(&g_hl[(size_t)s * 32 + lane]));
            }
        }
        float selfv = __half2float(g_hl[(size_t)node * 32 + lane]);
        float t = (a0 + a1) + (a2 + a3) + selfv;

        const float2* sWp = reinterpret_cast<const float2*>(sW);
        float o0 = 0.f, o1 = 0.f;
#pragma unroll
        for (int kk = 0; kk < 32; kk++) {
            float xv = __shfl_sync(0xFFFFFFFFu, t, kk);
            float2 w = sWp[kk * 32 + lane];
            o0 = fmaf(xv, w.x, o0);
            o1 = fmaf(xv, w.y, o1);
        }
        float d = g_dis[node];
        float2 bb = reinterpret_cast<const float2*>(b2)[lane];
        float2 o;
        o.x = d * o0 + bb.x;
        o.y = d * o1 + bb.y;
        sv[wid][lane] = o;
    }
    __syncthreads();

    if (threadIdx.x < 64) {
        int f = threadIdx.x;
        int half_ = f >> 1;
        int comp = f & 1;
        int curg = -1;
        float mx = FNEG_INF;
        for (int w = 0; w < 8; w++) {
            int bg = sb[w];
            if (bg < 0) continue;
            float2 p = sv[w][half_];
            float val = comp ? p.y : p.x;
            if (bg != curg) {
                if (curg >= 0) atomicMax(&g_pool[curg * 64 + f], fenc(mx));
                curg = bg;
                mx = FNEG_INF;
            }
            mx = fmaxf(mx, val);
        }
        if (curg >= 0) atomicMax(&g_pool[curg * 64 + f], fenc(mx));
    }
}

// MLP head, one block per graph: 64 -> 128 -> 64 -> 1
__global__ void k_mlp(const float* __restrict__ Wl1, const float* __restrict__ bl1,
                      const float* __restrict__ Wl2, const float* __restrict__ bl2,
                      const float* __restrict__ Wl3, const float* __restrict__ bl3,
                      float* __restrict__ out) {
    __shared__ float sg[64];
    __shared__ float st1[128];
    __shared__ float st2[64];
    int g = blockIdx.x;
    int t = threadIdx.x;

    if (t < 64) sg[t] = fdec(g_pool[g * 64 + t]);
    __syncthreads();
    {
        float s = bl1[t];
#pragma unroll 8
        for (int k = 0; k < 64; k++) s = fmaf(sg[k], Wl1[k * 128 + t], s);
        st1[t] = lrelu(s);
    }
    __syncthreads();
    if (t < 64) {
        float s = bl2[t];
#pragma unroll 8
        for (int k = 0; k < 128; k++) s = fmaf(st1[k], Wl2[k * 64 + t], s);
        st2[t] = lrelu(s);
    }
    __syncthreads();
    __shared__ float red[2];
    if (t < 64) {
        float p = st2[t] * Wl3[t];
#pragma unroll
        for (int off = 16; off > 0; off >>= 1)
            p += __shfl_down_sync(0xFFFFFFFFu, p, off);
        if ((t & 31) == 0) red[t >> 5] = p;
    }
    __syncthreads();
    if (t == 0) out[g] = red[0] + red[1] + bl3[0];
}

// ---------------- launch ----------------
// s2: memset, count, scanlb(evDis), fill(evCSR)
// main: gemm1(0) [waits evDis, overlaps fill], nop(1), agg1(2) [waits evCSR],
//       agg2(3) <- ncu capture, mlp(4)
extern "C" void kernel_launch(void* const* d_in, const int* in_sizes, int n_in,
                              void* d_out, int out_size) {
    const float* x   = (const float*)d_in[0];
    const int*   ei  = (const int*)d_in[1];
    const int*   bat = (const int*)d_in[2];
    const float* W1  = (const float*)d_in[3];
    const float* b1  = (const float*)d_in[4];
    const float* W2  = (const float*)d_in[5];
    const float* b2  = (const float*)d_in[6];
    const float* Wl1 = (const float*)d_in[7];
    const float* bl1 = (const float*)d_in[8];
    const float* Wl2 = (const float*)d_in[9];
    const float* bl2 = (const float*)d_in[10];
    const float* Wl3 = (const float*)d_in[11];
    const float* bl3 = (const float*)d_in[12];
    float* out = (float*)d_out;

    int Nn = in_sizes[0] / 128;
    int E  = in_sizes[1] / 2;
    const int* src = ei;
    const int* dst = ei + E;
    int NB = (Nn + 1023) / 1024;

    static cudaStream_t s2 = nullptr;
    static cudaEvent_t evFork = nullptr, evDis = nullptr, evCSR = nullptr;
    static void* cntPtr = nullptr;
    if (s2 == nullptr) {
        cudaStreamCreateWithFlags(&s2, cudaStreamNonBlocking);
        cudaEventCreateWithFlags(&evFork, cudaEventDisableTiming);
        cudaEventCreateWithFlags(&evDis, cudaEventDisableTiming);
        cudaEventCreateWithFlags(&evCSR, cudaEventDisableTiming);
        cudaGetSymbolAddress(&cntPtr, g_cnt);
    }

    // fork s2 off the captured (main) stream
    cudaEventRecord(evFork, 0);
    cudaStreamWaitEvent(s2, evFork, 0);

    // s2: CSR build chain
    cudaMemsetAsync(cntPtr, 0, NNODES * sizeof(int), s2);
    {
        int nThreads = (E >> 2) + (E & 3);
        k_count<<<(nThreads + 255) / 256, 256, 0, s2>>>(dst, E);
    }
    k_scanlb<<<NB, 256, 0, s2>>>(Nn);          // dis ready here
    cudaEventRecord(evDis, s2);
    {
        int nThreads = (E >> 2) + (E & 3);
        k_fill<<<(nThreads + 255) / 256, 256, 0, s2>>>(src, dst, E);
    }
    cudaEventRecord(evCSR, s2);

    // main: gemm1 (waits dis) overlaps fill on s2
    cudaStreamWaitEvent(0, evDis, 0);
    k_gemm1<<<(Nn + 31) / 32, 256>>>(x, W1, Nn);     // main idx 0 (4 nodes/warp)
    k_nop<<<1, 32>>>();                               // main idx 1

    // main: aggregation tail (waits CSR)
    cudaStreamWaitEvent(0, evCSR, 0);
    k_agg1<<<(Nn + 7) / 8, 256>>>(b1, Nn);           // main idx 2
    k_agg2<<<(Nn + 7) / 8, 256>>>(b2, W2, bat, Nn);  // main idx 3  <- ncu capture
    k_mlp<<<NGRAPH, 128>>>(Wl1, bl1, Wl2, bl2, Wl3, bl3, out);  // main idx 4
}